// round 4
// baseline (speedup 1.0000x reference)
#include <cuda_runtime.h>
#include <math.h>

#define TT 256
#define BB 64
#define HH 512
#define G4 2048
#define MM 16384   // T*B
#define NEGV -10000.0f

typedef unsigned long long ull;

// ---------------- scratch (device globals; no allocation allowed) ----------------
__device__ float g_xg[(size_t)2*MM*G4];      // per-dir input gates (+biases): 256 MB
__device__ float g_hseq0[(size_t)MM*1024];   // layer0 output [t*64+b][hf|hb]
__device__ float g_hseq1[(size_t)MM*1024];   // layer1 output
__device__ float g_h[2*2*BB*HH];             // [parity][dir][b][h] ping-pong
__device__ float g_c[2*BB*HH];               // [dir][b][h]
__device__ float g_feats[MM*4];
__device__ unsigned char g_bp[TT*BB*4];

__device__ __forceinline__ float sigf(float x){ return 1.0f/(1.0f+expf(-x)); }

__device__ __forceinline__ ull dup2(float x){
    unsigned u = __float_as_uint(x);
    return (ull)u | ((ull)u << 32);
}
__device__ __forceinline__ float lo32(ull v){ return __uint_as_float((unsigned)v); }
__device__ __forceinline__ float hi32(ull v){ return __uint_as_float((unsigned)(v >> 32)); }

#define FFMA2(d, a, b) asm("fma.rn.f32x2 %0, %1, %2, %0;" : "+l"(d) : "l"(a), "l"(b))

// ---------------- input-gate GEMM:  xg[d][r][n] = A[r]·W_d[n] + bih[n]+bhh[n] ----------------
// Tile 128x128, BK=8 double-buffered, 256 thr, 8x8 micro-tile via f32x2 (4 row-pairs x 8 cols).
template<bool GATHER>
__global__ void __launch_bounds__(256) xgates_kernel(
    const float* __restrict__ emb, const int* __restrict__ sent,
    const float* __restrict__ Wf, const float* __restrict__ Wb,
    const float* __restrict__ bihf, const float* __restrict__ bhhf,
    const float* __restrict__ bihb, const float* __restrict__ bhhb,
    int K)
{
    __shared__ float As[2][8][128];
    __shared__ float Bsm[2][8][128];
    const int tid = threadIdx.x;
    const int dir = blockIdx.z;
    const float* W   = dir ? Wb   : Wf;
    const float* bih = dir ? bihb : bihf;
    const float* bhh = dir ? bhhb : bhhf;
    const int m_base = blockIdx.y * 128;
    const int n_base = blockIdx.x * 128;

    // loader mapping: each thread loads one float4 of A and one of B per iter
    const int mL = tid & 127;
    const int kq = tid >> 7;            // 0..1 -> k offset kq*4
    const float* aRow;
    if (GATHER) {
        int row = m_base + mL;
        int t = row >> 6, b = row & 63;
        aRow = emb + (size_t)sent[b*TT + t] * 256;
    } else {
        aRow = g_hseq0 + (size_t)(m_base + mL) * 1024;
    }
    const float* wRow = W + (size_t)(n_base + mL) * K;

    // compute mapping: 16 row-groups x 16 col-groups
    const int rowg = tid & 15, colg = tid >> 4;
    const int m0 = rowg * 8, n0 = colg * 8;

    ull acc[4][8];
    #pragma unroll
    for (int p = 0; p < 4; p++)
        #pragma unroll
        for (int j = 0; j < 8; j++) acc[p][j] = 0ULL;

    const int iters = K >> 3;

    // prologue: tile 0 -> buf 0
    {
        float4 av = *(const float4*)(aRow + kq*4);
        As[0][kq*4+0][mL] = av.x; As[0][kq*4+1][mL] = av.y;
        As[0][kq*4+2][mL] = av.z; As[0][kq*4+3][mL] = av.w;
        float4 bv = *(const float4*)(wRow + kq*4);
        Bsm[0][kq*4+0][mL] = bv.x; Bsm[0][kq*4+1][mL] = bv.y;
        Bsm[0][kq*4+2][mL] = bv.z; Bsm[0][kq*4+3][mL] = bv.w;
    }
    __syncthreads();

    for (int it = 0; it < iters; it++) {
        const int buf = it & 1;
        float4 av, bv;
        const bool more = (it + 1 < iters);
        if (more) {
            int kt = (it + 1) * 8;
            av = *(const float4*)(aRow + kt + kq*4);
            bv = *(const float4*)(wRow + kt + kq*4);
        }
        #pragma unroll
        for (int k = 0; k < 8; k++) {
            ull a2[4];
            #pragma unroll
            for (int p = 0; p < 4; p++)
                a2[p] = *(const ull*)&As[buf][k][m0 + 2*p];
            float4 b0 = *(const float4*)&Bsm[buf][k][n0];
            float4 b1 = *(const float4*)&Bsm[buf][k][n0 + 4];
            ull b2[8];
            b2[0]=dup2(b0.x); b2[1]=dup2(b0.y); b2[2]=dup2(b0.z); b2[3]=dup2(b0.w);
            b2[4]=dup2(b1.x); b2[5]=dup2(b1.y); b2[6]=dup2(b1.z); b2[7]=dup2(b1.w);
            #pragma unroll
            for (int p = 0; p < 4; p++)
                #pragma unroll
                for (int j = 0; j < 8; j++)
                    FFMA2(acc[p][j], a2[p], b2[j]);
        }
        if (more) {
            int bufn = buf ^ 1;
            As[bufn][kq*4+0][mL] = av.x; As[bufn][kq*4+1][mL] = av.y;
            As[bufn][kq*4+2][mL] = av.z; As[bufn][kq*4+3][mL] = av.w;
            Bsm[bufn][kq*4+0][mL] = bv.x; Bsm[bufn][kq*4+1][mL] = bv.y;
            Bsm[bufn][kq*4+2][mL] = bv.z; Bsm[bufn][kq*4+3][mL] = bv.w;
        }
        __syncthreads();
    }

    // epilogue: add biases, store
    float4 bi0 = *(const float4*)(bih + n_base + n0);
    float4 bi1 = *(const float4*)(bih + n_base + n0 + 4);
    float4 bh0 = *(const float4*)(bhh + n_base + n0);
    float4 bh1 = *(const float4*)(bhh + n_base + n0 + 4);
    float badd[8] = {bi0.x+bh0.x, bi0.y+bh0.y, bi0.z+bh0.z, bi0.w+bh0.w,
                     bi1.x+bh1.x, bi1.y+bh1.y, bi1.z+bh1.z, bi1.w+bh1.w};
    #pragma unroll
    for (int p = 0; p < 4; p++) {
        int r0 = m_base + m0 + 2*p;
        float ve[8], vo[8];
        #pragma unroll
        for (int j = 0; j < 8; j++) {
            ve[j] = lo32(acc[p][j]) + badd[j];
            vo[j] = hi32(acc[p][j]) + badd[j];
        }
        float* dst0 = &g_xg[((size_t)dir*MM + r0)*G4 + n_base + n0];
        float* dst1 = &g_xg[((size_t)dir*MM + r0 + 1)*G4 + n_base + n0];
        *(float4*)(dst0)     = make_float4(ve[0], ve[1], ve[2], ve[3]);
        *(float4*)(dst0 + 4) = make_float4(ve[4], ve[5], ve[6], ve[7]);
        *(float4*)(dst1)     = make_float4(vo[0], vo[1], vo[2], vo[3]);
        *(float4*)(dst1 + 4) = make_float4(vo[4], vo[5], vo[6], vo[7]);
    }
}

// ---------------- state init ----------------
__global__ void init_state(const float* __restrict__ h0, const float* __restrict__ c0, int layer)
{
    int idx = blockIdx.x * blockDim.x + threadIdx.x;
    if (idx >= 2*BB*HH) return;
    g_h[idx] = h0[(size_t)layer*2*BB*HH + idx];   // parity 0 region = [dir][b][h]
    g_c[idx] = c0[(size_t)layer*2*BB*HH + idx];
}

// ---------------- fused recurrent step ----------------
// grid 128 = 2 dirs x 64 hidden-tiles(8 units); block 256 thr computes 64(batch) x 32 gate-cols
// thread-tile 2 rows x 4 cols via f32x2; B duplicated in smem as ull; BK=16 double-buffered.
__global__ void __launch_bounds__(256) lstm_step_kernel(
    const float* __restrict__ Whhf, const float* __restrict__ Whhb,
    int s, int parity, int layer)
{
    __shared__ float As[2][16][64];
    __shared__ ull   Bs[2][16][32];
    __shared__ float gsum[64][32];
    const int tid = threadIdx.x;
    const int dir = blockIdx.x >> 6;
    const int ht  = blockIdx.x & 63;
    const int j0  = ht * 8;
    const int t   = dir ? (TT-1-s) : s;
    const float* W = dir ? Whhb : Whhf;
    const float* hin  = g_h + ((size_t)parity*2 + dir)*BB*HH;
    float*       hout = g_h + ((size_t)(parity^1)*2 + dir)*BB*HH;
    float*       cptr = g_c + (size_t)dir*BB*HH;
    const float* xgrow_base = g_xg + ((size_t)dir*MM + (size_t)t*BB)*G4;
    float* hseq = layer ? g_hseq1 : g_hseq0;

    // loaders: A 64x16 floats = 256 float4 ; B 32x16 floats = 256 float2
    const int mA = tid & 63, kqA = tid >> 6;   // k offset kqA*4 (0..3)
    const int nB = tid & 31, kpB = tid >> 5;   // k offset kpB*2 (0..7)
    const int gB = nB >> 3, uB = nB & 7;
    const float* wRow = W + (size_t)(gB*HH + j0 + uB) * HH;
    const float* aRow = hin + (size_t)mA * HH;

    // compute mapping: 32 row-pairs x 8 col-quads
    const int rowg = tid & 31;     // rows 2*rowg, 2*rowg+1
    const int colg = tid >> 5;     // cols colg*4 .. +3

    ull acc[4] = {0ULL, 0ULL, 0ULL, 0ULL};

    // prologue: tile 0 -> buf 0
    {
        float4 av = *(const float4*)(aRow + kqA*4);
        As[0][kqA*4+0][mA] = av.x; As[0][kqA*4+1][mA] = av.y;
        As[0][kqA*4+2][mA] = av.z; As[0][kqA*4+3][mA] = av.w;
        float2 bv = *(const float2*)(wRow + kpB*2);
        Bs[0][kpB*2+0][nB] = dup2(bv.x);
        Bs[0][kpB*2+1][nB] = dup2(bv.y);
    }
    __syncthreads();

    #pragma unroll 1
    for (int it = 0; it < 32; it++) {
        const int buf = it & 1;
        float4 av; float2 bv;
        const bool more = (it + 1 < 32);
        if (more) {
            int kt = (it + 1) * 16;
            av = *(const float4*)(aRow + kt + kqA*4);
            bv = *(const float2*)(wRow + kt + kpB*2);
        }
        #pragma unroll
        for (int k = 0; k < 16; k++) {
            ull a2 = *(const ull*)&As[buf][k][rowg*2];
            ulonglong2 bb0 = *(const ulonglong2*)&Bs[buf][k][colg*4];
            ulonglong2 bb1 = *(const ulonglong2*)&Bs[buf][k][colg*4 + 2];
            FFMA2(acc[0], a2, bb0.x);
            FFMA2(acc[1], a2, bb0.y);
            FFMA2(acc[2], a2, bb1.x);
            FFMA2(acc[3], a2, bb1.y);
        }
        if (more) {
            int bufn = buf ^ 1;
            As[bufn][kqA*4+0][mA] = av.x; As[bufn][kqA*4+1][mA] = av.y;
            As[bufn][kqA*4+2][mA] = av.z; As[bufn][kqA*4+3][mA] = av.w;
            Bs[bufn][kpB*2+0][nB] = dup2(bv.x);
            Bs[bufn][kpB*2+1][nB] = dup2(bv.y);
        }
        __syncthreads();
    }

    // write partial sums to gsum
    #pragma unroll
    for (int j = 0; j < 4; j++) {
        gsum[2*rowg  ][colg*4 + j] = lo32(acc[j]);
        gsum[2*rowg+1][colg*4 + j] = hi32(acc[j]);
    }
    __syncthreads();

    // activations + state update: 512 (b,u) pairs, 2 per thread
    #pragma unroll
    for (int i = 0; i < 2; i++) {
        int it2 = tid + i*256;
        int b = it2 >> 3, u = it2 & 7;
        const float* xr = xgrow_base + (size_t)b*G4;
        float gi = gsum[b][ 0+u] + xr[0*HH + j0 + u];
        float gf = gsum[b][ 8+u] + xr[1*HH + j0 + u];
        float gg = gsum[b][16+u] + xr[2*HH + j0 + u];
        float go = gsum[b][24+u] + xr[3*HH + j0 + u];
        float cp = cptr[b*HH + j0 + u];
        float cn = sigf(gf)*cp + sigf(gi)*tanhf(gg);
        float hn = sigf(go)*tanhf(cn);
        cptr[b*HH + j0 + u] = cn;
        hout[b*HH + j0 + u] = hn;
        hseq[((size_t)t*BB + b)*1024 + dir*HH + j0 + u] = hn;
    }
}

// ---------------- feats: [16384,4] = hseq1 @ w_out^T + b_out ----------------
__global__ void __launch_bounds__(128) feats_kernel(const float* __restrict__ w_out,
                                                    const float* __restrict__ b_out)
{
    __shared__ float red[128][4];
    int r = blockIdx.x, tid = threadIdx.x;
    const float* x = g_hseq1 + (size_t)r * 1024;
    float a0=0.f, a1=0.f, a2=0.f, a3=0.f;
    for (int k = tid; k < 1024; k += 128) {
        float xv = x[k];
        a0 += xv * w_out[k];
        a1 += xv * w_out[1024 + k];
        a2 += xv * w_out[2048 + k];
        a3 += xv * w_out[3072 + k];
    }
    red[tid][0]=a0; red[tid][1]=a1; red[tid][2]=a2; red[tid][3]=a3;
    __syncthreads();
    for (int off = 64; off > 0; off >>= 1) {
        if (tid < off) {
            red[tid][0]+=red[tid+off][0]; red[tid][1]+=red[tid+off][1];
            red[tid][2]+=red[tid+off][2]; red[tid][3]+=red[tid+off][3];
        }
        __syncthreads();
    }
    if (tid < 4) g_feats[r*4 + tid] = red[0][tid] + b_out[tid];
}

// ---------------- Viterbi (K=4), single block; out = [score(64) | path(64x256)] as f32 ----------------
__global__ void viterbi_kernel(const float* __restrict__ trans, float* __restrict__ out)
{
    __shared__ float fv[64][4];
    __shared__ float tr[4][4];
    int tid = threadIdx.x;
    if (tid < 16) tr[tid>>2][tid&3] = trans[tid];
    int b = tid >> 2, nx = tid & 3;
    fv[b][nx] = (nx == 2) ? 0.0f : NEGV;   // START = 2
    __syncthreads();

    for (int t = 0; t < TT; t++) {
        float best = fv[b][0] + tr[nx][0];
        int arg = 0;
        #pragma unroll
        for (int p = 1; p < 4; p++) {
            float sc = fv[b][p] + tr[nx][p];
            if (sc > best) { best = sc; arg = p; }
        }
        float nf = best + g_feats[((size_t)t*BB + b)*4 + nx];
        g_bp[((size_t)t*BB + b)*4 + nx] = (unsigned char)arg;
        __syncthreads();
        fv[b][nx] = nf;
        __syncthreads();
    }

    if (tid < 64) {
        int bb = tid;
        float best = fv[bb][0] + tr[3][0];   // STOP = 3
        int arg = 0;
        #pragma unroll
        for (int k = 1; k < 4; k++) {
            float sc = fv[bb][k] + tr[3][k];
            if (sc > best) { best = sc; arg = k; }
        }
        out[bb] = best;
        int tag = arg;
        out[64 + bb*TT + (TT-1)] = (float)tag;
        for (int t = TT-2; t >= 0; --t) {
            tag = g_bp[((size_t)(t+1)*BB + bb)*4 + tag];
            out[64 + bb*TT + t] = (float)tag;
        }
    }
}

// ---------------- driver ----------------
extern "C" void kernel_launch(void* const* d_in, const int* in_sizes, int n_in,
                              void* d_out, int out_size)
{
    const int*   sent  = (const int*)  d_in[0];
    const float* emb   = (const float*)d_in[1];
    const float* wih0f = (const float*)d_in[2];
    const float* whh0f = (const float*)d_in[3];
    const float* bih0f = (const float*)d_in[4];
    const float* bhh0f = (const float*)d_in[5];
    const float* wih0b = (const float*)d_in[6];
    const float* whh0b = (const float*)d_in[7];
    const float* bih0b = (const float*)d_in[8];
    const float* bhh0b = (const float*)d_in[9];
    const float* wih1f = (const float*)d_in[10];
    const float* whh1f = (const float*)d_in[11];
    const float* bih1f = (const float*)d_in[12];
    const float* bhh1f = (const float*)d_in[13];
    const float* wih1b = (const float*)d_in[14];
    const float* whh1b = (const float*)d_in[15];
    const float* bih1b = (const float*)d_in[16];
    const float* bhh1b = (const float*)d_in[17];
    const float* h0    = (const float*)d_in[18];
    const float* c0    = (const float*)d_in[19];
    const float* w_out = (const float*)d_in[20];
    const float* b_out = (const float*)d_in[21];
    const float* trans = (const float*)d_in[22];
    float* out = (float*)d_out;

    dim3 gx(16, 128, 2);   // ntiles(2048/128)=16, mtiles(16384/128)=128, dirs=2

    // layer 0
    xgates_kernel<true><<<gx, 256>>>(emb, sent, wih0f, wih0b, bih0f, bhh0f, bih0b, bhh0b, 256);
    init_state<<<(2*BB*HH + 255)/256, 256>>>(h0, c0, 0);
    for (int s = 0; s < TT; s++)
        lstm_step_kernel<<<128, 256>>>(whh0f, whh0b, s, s & 1, 0);

    // layer 1
    xgates_kernel<false><<<gx, 256>>>(emb, sent, wih1f, wih1b, bih1f, bhh1f, bih1b, bhh1b, 1024);
    init_state<<<(2*BB*HH + 255)/256, 256>>>(h0, c0, 1);
    for (int s = 0; s < TT; s++)
        lstm_step_kernel<<<128, 256>>>(whh1f, whh1b, s, s & 1, 1);

    // emissions + decode
    feats_kernel<<<MM, 128>>>(w_out, b_out);
    viterbi_kernel<<<1, 256>>>(trans, out);
}

// round 7
// speedup vs baseline: 1.5841x; 1.5841x over previous
#include <cuda_runtime.h>
#include <math.h>

#define TT 256
#define BB 64
#define HH 512
#define G4 2048
#define MM 16384   // T*B
#define NEGV -10000.0f

typedef unsigned long long ull;

// ---------------- scratch (device globals; no allocation allowed) ----------------
__device__ float g_xg[(size_t)2*MM*G4];      // per-dir input gates (+biases): 256 MB
__device__ float g_hseq0[(size_t)MM*1024];   // layer0 output [t*64+b][hf|hb]
__device__ float g_hseq1[(size_t)MM*1024];   // layer1 output
__device__ float g_h[2*2*HH*BB];             // [parity][dir][h][b]  (transposed!)
__device__ float g_feats[MM*4];
__device__ unsigned char g_bp[TT*BB*4];
__device__ unsigned g_bar;                   // grid barrier counter

__device__ __forceinline__ float sigf(float x){ return 1.0f/(1.0f+expf(-x)); }

__device__ __forceinline__ ull dup2(float x){
    unsigned u = __float_as_uint(x);
    return (ull)u | ((ull)u << 32);
}
__device__ __forceinline__ float lo32(ull v){ return __uint_as_float((unsigned)v); }
__device__ __forceinline__ float hi32(ull v){ return __uint_as_float((unsigned)(v >> 32)); }

#define FFMA2(d, a, b) asm("fma.rn.f32x2 %0, %1, %2, %0;" : "+l"(d) : "l"(a), "l"(b))

// all 128 blocks co-resident (1 block/SM). classic CG-style grid sync.
__device__ __forceinline__ void grid_barrier()
{
    __syncthreads();
    if (threadIdx.x == 0) {
        __threadfence();
        unsigned my = atomicAdd(&g_bar, 1u);
        unsigned target = (my / 128u + 1u) * 128u;
        while (*(volatile unsigned*)&g_bar < target) { }
        __threadfence();
    }
    __syncthreads();
}

// ---------------- input-gate GEMM:  xg[d][r][n] = A[r]·W_d[n] + bih[n]+bhh[n] ----------------
template<bool GATHER>
__global__ void __launch_bounds__(256) xgates_kernel(
    const float* __restrict__ emb, const int* __restrict__ sent,
    const float* __restrict__ Wf, const float* __restrict__ Wb,
    const float* __restrict__ bihf, const float* __restrict__ bhhf,
    const float* __restrict__ bihb, const float* __restrict__ bhhb,
    int K)
{
    __shared__ float As[2][8][128];
    __shared__ float Bsm[2][8][128];
    const int tid = threadIdx.x;
    const int dir = blockIdx.z;
    const float* W   = dir ? Wb   : Wf;
    const float* bih = dir ? bihb : bihf;
    const float* bhh = dir ? bhhb : bhhf;
    const int m_base = blockIdx.y * 128;
    const int n_base = blockIdx.x * 128;

    const int mL = tid & 127;
    const int kq = tid >> 7;
    const float* aRow;
    if (GATHER) {
        int row = m_base + mL;
        int t = row >> 6, b = row & 63;
        aRow = emb + (size_t)sent[b*TT + t] * 256;
    } else {
        aRow = g_hseq0 + (size_t)(m_base + mL) * 1024;
    }
    const float* wRow = W + (size_t)(n_base + mL) * K;

    const int rowg = tid & 15, colg = tid >> 4;
    const int m0 = rowg * 8, n0 = colg * 8;

    ull acc[4][8];
    #pragma unroll
    for (int p = 0; p < 4; p++)
        #pragma unroll
        for (int j = 0; j < 8; j++) acc[p][j] = 0ULL;

    const int iters = K >> 3;

    {
        float4 av = *(const float4*)(aRow + kq*4);
        As[0][kq*4+0][mL] = av.x; As[0][kq*4+1][mL] = av.y;
        As[0][kq*4+2][mL] = av.z; As[0][kq*4+3][mL] = av.w;
        float4 bv = *(const float4*)(wRow + kq*4);
        Bsm[0][kq*4+0][mL] = bv.x; Bsm[0][kq*4+1][mL] = bv.y;
        Bsm[0][kq*4+2][mL] = bv.z; Bsm[0][kq*4+3][mL] = bv.w;
    }
    __syncthreads();

    for (int it = 0; it < iters; it++) {
        const int buf = it & 1;
        float4 av, bv;
        const bool more = (it + 1 < iters);
        if (more) {
            int kt = (it + 1) * 8;
            av = *(const float4*)(aRow + kt + kq*4);
            bv = *(const float4*)(wRow + kt + kq*4);
        }
        #pragma unroll
        for (int k = 0; k < 8; k++) {
            ull a2[4];
            #pragma unroll
            for (int p = 0; p < 4; p++)
                a2[p] = *(const ull*)&As[buf][k][m0 + 2*p];
            float4 b0 = *(const float4*)&Bsm[buf][k][n0];
            float4 b1 = *(const float4*)&Bsm[buf][k][n0 + 4];
            ull b2[8];
            b2[0]=dup2(b0.x); b2[1]=dup2(b0.y); b2[2]=dup2(b0.z); b2[3]=dup2(b0.w);
            b2[4]=dup2(b1.x); b2[5]=dup2(b1.y); b2[6]=dup2(b1.z); b2[7]=dup2(b1.w);
            #pragma unroll
            for (int p = 0; p < 4; p++)
                #pragma unroll
                for (int j = 0; j < 8; j++)
                    FFMA2(acc[p][j], a2[p], b2[j]);
        }
        if (more) {
            int bufn = buf ^ 1;
            As[bufn][kq*4+0][mL] = av.x; As[bufn][kq*4+1][mL] = av.y;
            As[bufn][kq*4+2][mL] = av.z; As[bufn][kq*4+3][mL] = av.w;
            Bsm[bufn][kq*4+0][mL] = bv.x; Bsm[bufn][kq*4+1][mL] = bv.y;
            Bsm[bufn][kq*4+2][mL] = bv.z; Bsm[bufn][kq*4+3][mL] = bv.w;
        }
        __syncthreads();
    }

    float4 bi0 = *(const float4*)(bih + n_base + n0);
    float4 bi1 = *(const float4*)(bih + n_base + n0 + 4);
    float4 bh0 = *(const float4*)(bhh + n_base + n0);
    float4 bh1 = *(const float4*)(bhh + n_base + n0 + 4);
    float badd[8] = {bi0.x+bh0.x, bi0.y+bh0.y, bi0.z+bh0.z, bi0.w+bh0.w,
                     bi1.x+bh1.x, bi1.y+bh1.y, bi1.z+bh1.z, bi1.w+bh1.w};
    #pragma unroll
    for (int p = 0; p < 4; p++) {
        int r0 = m_base + m0 + 2*p;
        float ve[8], vo[8];
        #pragma unroll
        for (int j = 0; j < 8; j++) {
            ve[j] = lo32(acc[p][j]) + badd[j];
            vo[j] = hi32(acc[p][j]) + badd[j];
        }
        float* dst0 = &g_xg[((size_t)dir*MM + r0)*G4 + n_base + n0];
        float* dst1 = &g_xg[((size_t)dir*MM + r0 + 1)*G4 + n_base + n0];
        *(float4*)(dst0)     = make_float4(ve[0], ve[1], ve[2], ve[3]);
        *(float4*)(dst0 + 4) = make_float4(ve[4], ve[5], ve[6], ve[7]);
        *(float4*)(dst1)     = make_float4(vo[0], vo[1], vo[2], vo[3]);
        *(float4*)(dst1 + 4) = make_float4(vo[4], vo[5], vo[6], vo[7]);
    }
}

// ---------------- state init: h0 -> transposed parity-0 g_h, reset barrier ----------------
__global__ void init_state(const float* __restrict__ h0, int layer)
{
    if (blockIdx.x == 0 && threadIdx.x == 0) g_bar = 0u;
    int idx = blockIdx.x * blockDim.x + threadIdx.x;   // 0 .. 2*512*64-1
    if (idx >= 2*HH*BB) return;
    int dir = idx >> 15;
    int rem = idx & 32767;            // h*64 + b
    int h = rem >> 6, b = rem & 63;
    g_h[(size_t)dir*HH*BB + rem] = h0[((size_t)(layer*2 + dir)*BB + b)*HH + h];
}

// ---------------- persistent recurrent layer ----------------
// 128 blocks (2 dir x 64 unit-tiles of 8) x 128 thr; W dup'd in smem; 256 steps in-kernel.
#define SM_AS   131072
#define SM_GS   (131072 + 32768)
#define SM_TOT  (131072 + 32768 + 8448)

__global__ void __launch_bounds__(128, 1) lstm_layer_kernel(
    const float* __restrict__ Whhf, const float* __restrict__ Whhb,
    const float* __restrict__ c0, int layer)
{
    extern __shared__ unsigned char sraw[];
    ull*   Bs   = (ull*)sraw;                       // [512][32] dup'd
    float* As   = (float*)(sraw + SM_AS);           // [2][64 k][64 b]
    float* gsum = (float*)(sraw + SM_GS);           // [64][33]

    const int tid = threadIdx.x;
    const int bx  = blockIdx.x;
    const int dir = bx >> 6;
    const int ct  = bx & 63;
    const int j0  = ct * 8;
    const float* W = dir ? Whhb : Whhf;
    float* hseq = layer ? g_hseq1 : g_hseq0;

    // one-time: W slice (32 gate-cols x 512 k) duplicated into smem
    {
        const int c = tid >> 2;            // 0..31 : gate g=c>>3, unit u=c&7
        const int seg = tid & 3;           // 128-k segment
        const float* wp = W + (size_t)((c >> 3)*HH + j0 + (c & 7))*HH + seg*128;
        #pragma unroll
        for (int i = 0; i < 32; i++) {
            float4 v = *(const float4*)(wp + i*4);
            int k = seg*128 + i*4;
            Bs[(size_t)(k+0)*32 + c] = dup2(v.x);
            Bs[(size_t)(k+1)*32 + c] = dup2(v.y);
            Bs[(size_t)(k+2)*32 + c] = dup2(v.z);
            Bs[(size_t)(k+3)*32 + c] = dup2(v.w);
        }
    }
    // c state in registers: pair idx = i*128+tid -> (u=idx>>6, b=idx&63)
    float creg[4];
    #pragma unroll
    for (int i = 0; i < 4; i++) {
        int idx = i*128 + tid;
        int u = idx >> 6, b = idx & 63;
        creg[i] = c0[((size_t)(layer*2 + dir)*BB + b)*HH + j0 + u];
    }
    __syncthreads();

    // compute mapping: thread tile = 4 batches x 4 cols
    const int lane = tid & 31, w = tid >> 5;
    const int rowg = lane & 15, colh = lane >> 4;
    const int r0  = rowg * 4;
    const int c0i = w*8 + colh*4;

    for (int s = 0; s < TT; s++) {
        const int t = dir ? (TT-1-s) : s;
        const int parity = s & 1;
        const float* hin = g_h + ((size_t)parity*2 + dir)*HH*BB;   // [k][b]

        // chunk 0 -> buf 0 (bypass L1: g_h is cross-SM mutable)
        #pragma unroll
        for (int i = 0; i < 8; i++) {
            int f = i*128 + tid;            // float4 unit
            int k = f >> 4, b4 = (f & 15)*4;
            float4 v = __ldcg((const float4*)(hin + k*64 + b4));
            *(float4*)&As[k*64 + b4] = v;
        }
        __syncthreads();

        ull a00=0,a01=0,a02=0,a03=0,a10=0,a11=0,a12=0,a13=0;

        for (int kc = 0; kc < 8; kc++) {
            const int buf = kc & 1;
            float4 pf[8];
            if (kc < 7) {
                #pragma unroll
                for (int i = 0; i < 8; i++) {
                    int f = i*128 + tid;
                    int k = f >> 4, b4 = (f & 15)*4;
                    pf[i] = __ldcg((const float4*)(hin + ((kc+1)*64 + k)*64 + b4));
                }
            }
            const float* ap = As + buf*4096 + r0;
            const ull*   bp = Bs + (size_t)(kc*64)*32 + c0i;
            #pragma unroll 8
            for (int kk = 0; kk < 64; kk++) {
                float4 a = *(const float4*)(ap + kk*64);
                ull al = *(const ull*)&a.x;     // batches r0, r0+1
                ull ah = *(const ull*)&a.z;     // batches r0+2, r0+3
                ulonglong2 b01 = *(const ulonglong2*)(bp + kk*32);
                ulonglong2 b23 = *(const ulonglong2*)(bp + kk*32 + 2);
                FFMA2(a00, al, b01.x); FFMA2(a01, al, b01.y);
                FFMA2(a02, al, b23.x); FFMA2(a03, al, b23.y);
                FFMA2(a10, ah, b01.x); FFMA2(a11, ah, b01.y);
                FFMA2(a12, ah, b23.x); FFMA2(a13, ah, b23.y);
            }
            if (kc < 7) {
                float* ad = As + (buf^1)*4096;
                #pragma unroll
                for (int i = 0; i < 8; i++) {
                    int f = i*128 + tid;
                    int k = f >> 4, b4 = (f & 15)*4;
                    *(float4*)&ad[k*64 + b4] = pf[i];
                }
            }
            __syncthreads();
        }

        // stash gate partials
        gsum[(r0+0)*33 + c0i+0] = lo32(a00); gsum[(r0+0)*33 + c0i+1] = lo32(a01);
        gsum[(r0+0)*33 + c0i+2] = lo32(a02); gsum[(r0+0)*33 + c0i+3] = lo32(a03);
        gsum[(r0+1)*33 + c0i+0] = hi32(a00); gsum[(r0+1)*33 + c0i+1] = hi32(a01);
        gsum[(r0+1)*33 + c0i+2] = hi32(a02); gsum[(r0+1)*33 + c0i+3] = hi32(a03);
        gsum[(r0+2)*33 + c0i+0] = lo32(a10); gsum[(r0+2)*33 + c0i+1] = lo32(a11);
        gsum[(r0+2)*33 + c0i+2] = lo32(a12); gsum[(r0+2)*33 + c0i+3] = lo32(a13);
        gsum[(r0+3)*33 + c0i+0] = hi32(a10); gsum[(r0+3)*33 + c0i+1] = hi32(a11);
        gsum[(r0+3)*33 + c0i+2] = hi32(a12); gsum[(r0+3)*33 + c0i+3] = hi32(a13);
        __syncthreads();

        // activations + state update
        float* hout = g_h + ((size_t)(parity^1)*2 + dir)*HH*BB;
        #pragma unroll
        for (int i = 0; i < 4; i++) {
            int idx = i*128 + tid;
            int u = idx >> 6, b = idx & 63;
            const float* xr = g_xg + ((size_t)dir*MM + (size_t)t*BB + b)*G4 + j0 + u;
            float gi = gsum[b*33 +  0 + u] + xr[0];
            float gf = gsum[b*33 +  8 + u] + xr[HH];
            float gg = gsum[b*33 + 16 + u] + xr[2*HH];
            float go = gsum[b*33 + 24 + u] + xr[3*HH];
            float cn = sigf(gf)*creg[i] + sigf(gi)*tanhf(gg);
            float hn = sigf(go)*tanhf(cn);
            creg[i] = cn;
            hout[(j0 + u)*BB + b] = hn;
            hseq[((size_t)t*BB + b)*1024 + dir*HH + j0 + u] = hn;
        }

        if (s != TT-1) grid_barrier();
    }
}

// ---------------- feats ----------------
__global__ void __launch_bounds__(128) feats_kernel(const float* __restrict__ w_out,
                                                    const float* __restrict__ b_out)
{
    __shared__ float red[128][4];
    int r = blockIdx.x, tid = threadIdx.x;
    const float* x = g_hseq1 + (size_t)r * 1024;
    float s0=0.f, s1=0.f, s2=0.f, s3=0.f;
    for (int k = tid; k < 1024; k += 128) {
        float xv = x[k];
        s0 += xv * w_out[k];
        s1 += xv * w_out[1024 + k];
        s2 += xv * w_out[2048 + k];
        s3 += xv * w_out[3072 + k];
    }
    red[tid][0]=s0; red[tid][1]=s1; red[tid][2]=s2; red[tid][3]=s3;
    __syncthreads();
    for (int off = 64; off > 0; off >>= 1) {
        if (tid < off) {
            red[tid][0]+=red[tid+off][0]; red[tid][1]+=red[tid+off][1];
            red[tid][2]+=red[tid+off][2]; red[tid][3]+=red[tid+off][3];
        }
        __syncthreads();
    }
    if (tid < 4) g_feats[r*4 + tid] = red[0][tid] + b_out[tid];
}

// ---------------- Viterbi ----------------
__global__ void viterbi_kernel(const float* __restrict__ trans, float* __restrict__ out)
{
    __shared__ float fv[64][4];
    __shared__ float tr[4][4];
    int tid = threadIdx.x;
    if (tid < 16) tr[tid>>2][tid&3] = trans[tid];
    int b = tid >> 2, nx = tid & 3;
    fv[b][nx] = (nx == 2) ? 0.0f : NEGV;   // START = 2
    __syncthreads();

    for (int t = 0; t < TT; t++) {
        float best = fv[b][0] + tr[nx][0];
        int arg = 0;
        #pragma unroll
        for (int p = 1; p < 4; p++) {
            float sc = fv[b][p] + tr[nx][p];
            if (sc > best) { best = sc; arg = p; }
        }
        float nf = best + g_feats[((size_t)t*BB + b)*4 + nx];
        g_bp[((size_t)t*BB + b)*4 + nx] = (unsigned char)arg;
        __syncthreads();
        fv[b][nx] = nf;
        __syncthreads();
    }

    if (tid < 64) {
        int bb = tid;
        float best = fv[bb][0] + tr[3][0];   // STOP = 3
        int arg = 0;
        #pragma unroll
        for (int k = 1; k < 4; k++) {
            float sc = fv[bb][k] + tr[3][k];
            if (sc > best) { best = sc; arg = k; }
        }
        out[bb] = best;
        int tag = arg;
        out[64 + bb*TT + (TT-1)] = (float)tag;
        for (int t = TT-2; t >= 0; --t) {
            tag = g_bp[((size_t)(t+1)*BB + bb)*4 + tag];
            out[64 + bb*TT + t] = (float)tag;
        }
    }
}

// ---------------- driver (8 graph nodes) ----------------
extern "C" void kernel_launch(void* const* d_in, const int* in_sizes, int n_in,
                              void* d_out, int out_size)
{
    const int*   sent  = (const int*)  d_in[0];
    const float* emb   = (const float*)d_in[1];
    const float* wih0f = (const float*)d_in[2];
    const float* whh0f = (const float*)d_in[3];
    const float* bih0f = (const float*)d_in[4];
    const float* bhh0f = (const float*)d_in[5];
    const float* wih0b = (const float*)d_in[6];
    const float* whh0b = (const float*)d_in[7];
    const float* bih0b = (const float*)d_in[8];
    const float* bhh0b = (const float*)d_in[9];
    const float* wih1f = (const float*)d_in[10];
    const float* whh1f = (const float*)d_in[11];
    const float* bih1f = (const float*)d_in[12];
    const float* bhh1f = (const float*)d_in[13];
    const float* wih1b = (const float*)d_in[14];
    const float* whh1b = (const float*)d_in[15];
    const float* bih1b = (const float*)d_in[16];
    const float* bhh1b = (const float*)d_in[17];
    const float* h0    = (const float*)d_in[18];
    const float* c0    = (const float*)d_in[19];
    const float* w_out = (const float*)d_in[20];
    const float* b_out = (const float*)d_in[21];
    const float* trans = (const float*)d_in[22];
    float* out = (float*)d_out;

    cudaFuncSetAttribute(lstm_layer_kernel,
                         cudaFuncAttributeMaxDynamicSharedMemorySize, SM_TOT);

    dim3 gx(16, 128, 2);

    xgates_kernel<true><<<gx, 256>>>(emb, sent, wih0f, wih0b, bih0f, bhh0f, bih0b, bhh0b, 256);
    init_state<<<256, 256>>>(h0, 0);
    lstm_layer_kernel<<<128, 128, SM_TOT>>>(whh0f, whh0b, c0, 0);

    xgates_kernel<false><<<gx, 256>>>(emb, sent, wih1f, wih1b, bih1f, bhh1f, bih1b, bhh1b, 1024);
    init_state<<<256, 256>>>(h0, 1);
    lstm_layer_kernel<<<128, 128, SM_TOT>>>(whh1f, whh1b, c0, 1);

    feats_kernel<<<MM, 128>>>(w_out, b_out);
    viterbi_kernel<<<1, 256>>>(trans, out);
}